// round 1
// baseline (speedup 1.0000x reference)
#include <cuda_runtime.h>
#include <cuda_bf16.h>
#include <math.h>

// Problem constants
#define B_  4
#define S_  2048
#define E_  1024
#define H_  16
#define HD_ 64
#define BH_ (B_*H_)           // 64
#define N3E (3*E_)            // 3072

// Scratch (device globals; allocation-free)
__device__ float g_q[(size_t)BH_ * S_ * HD_];     // [B,H,S,HD]
__device__ float g_k[(size_t)BH_ * S_ * HD_];
__device__ float g_v[(size_t)BH_ * S_ * HD_];
__device__ float g_vals[(size_t)B_ * S_ * E_];    // [B,S,E] (=[B,S,H,HD])

// ---------------------------------------------------------------------------
// Kernel 1: QKV GEMM  C[8192,3072] = X[8192,1024] @ W[1024,3072] + bias,
// scattered into g_q/g_k/g_v with [B,H,S,HD] layout.
// 128x128x8 tiles, 256 threads, 8x8 per thread.
// ---------------------------------------------------------------------------
__global__ void __launch_bounds__(256) qkv_gemm_kernel(
    const float* __restrict__ X, const float* __restrict__ W,
    const float* __restrict__ bias)
{
    const int M = B_*S_, N = N3E, K = E_;
    __shared__ float As[8][128];
    __shared__ float Bs[8][128];
    int tid = threadIdx.x;
    int bx = blockIdx.x, by = blockIdx.y;

    int aRow = tid >> 1;            // 0..127
    int aCol = (tid & 1) * 4;       // 0 or 4
    int bRow = tid >> 5;            // 0..7
    int bCol = (tid & 31) * 4;      // 0..124
    int ty = tid >> 4, tx = tid & 15;

    float acc[8][8];
    #pragma unroll
    for (int i = 0; i < 8; i++)
        #pragma unroll
        for (int j = 0; j < 8; j++) acc[i][j] = 0.f;

    const float* Aptr = X + (size_t)(by*128 + aRow)*K + aCol;
    const float* Bptr = W + (size_t)bRow*N + bx*128 + bCol;

    for (int k0 = 0; k0 < K; k0 += 8) {
        float4 a4 = *(const float4*)(Aptr + k0);
        As[aCol+0][aRow] = a4.x; As[aCol+1][aRow] = a4.y;
        As[aCol+2][aRow] = a4.z; As[aCol+3][aRow] = a4.w;
        float4 b4 = *(const float4*)(Bptr + (size_t)k0*N);
        *(float4*)&Bs[bRow][bCol] = b4;
        __syncthreads();
        #pragma unroll
        for (int k = 0; k < 8; k++) {
            float ar[8], br[8];
            *(float4*)(ar)   = *(float4*)&As[k][ty*8];
            *(float4*)(ar+4) = *(float4*)&As[k][ty*8+4];
            *(float4*)(br)   = *(float4*)&Bs[k][tx*8];
            *(float4*)(br+4) = *(float4*)&Bs[k][tx*8+4];
            #pragma unroll
            for (int i = 0; i < 8; i++)
                #pragma unroll
                for (int j = 0; j < 8; j++)
                    acc[i][j] = fmaf(ar[i], br[j], acc[i][j]);
        }
        __syncthreads();
    }

    #pragma unroll
    for (int i = 0; i < 8; i++) {
        int m = by*128 + ty*8 + i;
        int bb = m >> 11;        // / 2048
        int s  = m & 2047;
        #pragma unroll
        for (int j = 0; j < 8; j++) {
            int n = bx*128 + tx*8 + j;
            float val = acc[i][j] + bias[n];
            int h = n / 192;
            int r = n - h*192;
            size_t base = (((size_t)bb*H_ + h)*S_ + s)*HD_;
            if (r < 64)       g_q[base + r]       = val;
            else if (r < 128) g_k[base + r - 64]  = val;
            else              g_v[base + r - 128] = val;
        }
    }
}

// ---------------------------------------------------------------------------
// Kernel 2: causal logits per head. 64x64 tiles. Tiles strictly above the
// diagonal are written as zeros. Writes scaled raw logits into attn buffer.
// ---------------------------------------------------------------------------
__global__ void __launch_bounds__(256) logits_kernel(float* __restrict__ attn)
{
    int head = blockIdx.z;
    int bxt = blockIdx.x;   // key tile
    int byt = blockIdx.y;   // query tile
    float* out = attn + (size_t)head * S_ * S_;
    int tid = threadIdx.x;
    int ty = tid >> 4, tx = tid & 15;

    if (bxt > byt) {   // fully masked tile -> zeros
        #pragma unroll
        for (int i = 0; i < 4; i++) {
            int row = byt*64 + ty*4 + i;
            float4 z = make_float4(0.f, 0.f, 0.f, 0.f);
            *(float4*)&out[(size_t)row*S_ + bxt*64 + tx*4] = z;
        }
        return;
    }

    __shared__ float Qs[64][65];   // [d][qrow]
    __shared__ float Ks[64][65];   // [d][kcol]
    const float* qbase = g_q + (size_t)head*S_*HD_;
    const float* kbase = g_k + (size_t)head*S_*HD_;

    for (int idx = tid; idx < 64*16; idx += 256) {
        int r = idx >> 4;          // 0..63
        int c = (idx & 15) * 4;    // 0..60
        float4 q4 = *(const float4*)&qbase[(size_t)(byt*64 + r)*HD_ + c];
        Qs[c+0][r] = q4.x; Qs[c+1][r] = q4.y; Qs[c+2][r] = q4.z; Qs[c+3][r] = q4.w;
        float4 k4 = *(const float4*)&kbase[(size_t)(bxt*64 + r)*HD_ + c];
        Ks[c+0][r] = k4.x; Ks[c+1][r] = k4.y; Ks[c+2][r] = k4.z; Ks[c+3][r] = k4.w;
    }
    __syncthreads();

    float acc[4][4];
    #pragma unroll
    for (int i = 0; i < 4; i++)
        #pragma unroll
        for (int j = 0; j < 4; j++) acc[i][j] = 0.f;

    #pragma unroll 8
    for (int k = 0; k < 64; k++) {
        float a0 = Qs[k][ty*4+0], a1 = Qs[k][ty*4+1], a2 = Qs[k][ty*4+2], a3 = Qs[k][ty*4+3];
        float b0 = Ks[k][tx*4+0], b1 = Ks[k][tx*4+1], b2 = Ks[k][tx*4+2], b3 = Ks[k][tx*4+3];
        acc[0][0] = fmaf(a0,b0,acc[0][0]); acc[0][1] = fmaf(a0,b1,acc[0][1]);
        acc[0][2] = fmaf(a0,b2,acc[0][2]); acc[0][3] = fmaf(a0,b3,acc[0][3]);
        acc[1][0] = fmaf(a1,b0,acc[1][0]); acc[1][1] = fmaf(a1,b1,acc[1][1]);
        acc[1][2] = fmaf(a1,b2,acc[1][2]); acc[1][3] = fmaf(a1,b3,acc[1][3]);
        acc[2][0] = fmaf(a2,b0,acc[2][0]); acc[2][1] = fmaf(a2,b1,acc[2][1]);
        acc[2][2] = fmaf(a2,b2,acc[2][2]); acc[2][3] = fmaf(a2,b3,acc[2][3]);
        acc[3][0] = fmaf(a3,b0,acc[3][0]); acc[3][1] = fmaf(a3,b1,acc[3][1]);
        acc[3][2] = fmaf(a3,b2,acc[3][2]); acc[3][3] = fmaf(a3,b3,acc[3][3]);
    }

    const float scale = 0.125f;   // 1/sqrt(64)
    #pragma unroll
    for (int i = 0; i < 4; i++) {
        int row = byt*64 + ty*4 + i;
        #pragma unroll
        for (int j = 0; j < 4; j++) {
            int col = bxt*64 + tx*4 + j;
            float v = acc[i][j] * scale;
            if (col > row) v = 0.f;      // masked (diagonal tiles)
            out[(size_t)row*S_ + col] = v;
        }
    }
}

// ---------------------------------------------------------------------------
// Kernel 3: row softmax in-place over the valid prefix [0, s].
// One block (256 threads) per row. Entries > s stay 0.
// ---------------------------------------------------------------------------
__global__ void __launch_bounds__(256) softmax_kernel(float* __restrict__ attn)
{
    __shared__ float red[8];
    int tid = threadIdx.x;
    size_t rowId = blockIdx.x;
    int s = (int)(rowId & (S_-1));
    float* row = attn + rowId * S_;
    int n = s + 1;

    float v[8];
    int cnt = 0;
    float m = -INFINITY;
    for (int i = tid; i < n; i += 256) {
        float x = row[i];
        v[cnt++] = x;
        m = fmaxf(m, x);
    }
    #pragma unroll
    for (int o = 16; o > 0; o >>= 1) m = fmaxf(m, __shfl_xor_sync(0xffffffffu, m, o));
    if ((tid & 31) == 0) red[tid >> 5] = m;
    __syncthreads();
    float bm = red[0];
    #pragma unroll
    for (int i = 1; i < 8; i++) bm = fmaxf(bm, red[i]);
    __syncthreads();

    float sum = 0.f;
    for (int j = 0; j < cnt; j++) { v[j] = __expf(v[j] - bm); sum += v[j]; }
    #pragma unroll
    for (int o = 16; o > 0; o >>= 1) sum += __shfl_xor_sync(0xffffffffu, sum, o);
    if ((tid & 31) == 0) red[tid >> 5] = sum;
    __syncthreads();
    float tot = 0.f;
    #pragma unroll
    for (int i = 0; i < 8; i++) tot += red[i];
    float inv = 1.f / tot;

    cnt = 0;
    for (int i = tid; i < n; i += 256) row[i] = v[cnt++] * inv;
}

// ---------------------------------------------------------------------------
// Kernel 4: vals = attn @ V per head (triangular k-range).
// 64x64 output tile (N = HD = 64 full), BK=16, 4x4 per thread.
// Writes into g_vals with [B,S,E] layout.
// ---------------------------------------------------------------------------
__global__ void __launch_bounds__(256) av_kernel(const float* __restrict__ attn)
{
    int head = blockIdx.z;
    int byt = blockIdx.y;
    const float* arow  = attn + (size_t)head * S_ * S_;
    const float* vbase = g_v + (size_t)head * S_ * HD_;
    int tid = threadIdx.x;
    int ty = tid >> 4, tx = tid & 15;

    __shared__ float As[16][65];   // [k][row]
    __shared__ float Bs[16][64];   // [k][d]
    float acc[4][4];
    #pragma unroll
    for (int i = 0; i < 4; i++)
        #pragma unroll
        for (int j = 0; j < 4; j++) acc[i][j] = 0.f;

    int ar = tid >> 2;          // 0..63
    int ac = (tid & 3) * 4;     // 0..12
    int vr = tid >> 4;          // 0..15
    int vc = (tid & 15) * 4;    // 0..60

    int kmax = byt*64 + 64;     // causal: no contributions past the diagonal
    for (int k0 = 0; k0 < kmax; k0 += 16) {
        float4 a4 = *(const float4*)&arow[(size_t)(byt*64 + ar)*S_ + k0 + ac];
        As[ac+0][ar] = a4.x; As[ac+1][ar] = a4.y; As[ac+2][ar] = a4.z; As[ac+3][ar] = a4.w;
        *(float4*)&Bs[vr][vc] = *(const float4*)&vbase[(size_t)(k0 + vr)*HD_ + vc];
        __syncthreads();
        #pragma unroll
        for (int k = 0; k < 16; k++) {
            float a0 = As[k][ty*4+0], a1 = As[k][ty*4+1], a2 = As[k][ty*4+2], a3 = As[k][ty*4+3];
            float b0 = Bs[k][tx*4+0], b1 = Bs[k][tx*4+1], b2 = Bs[k][tx*4+2], b3 = Bs[k][tx*4+3];
            acc[0][0] = fmaf(a0,b0,acc[0][0]); acc[0][1] = fmaf(a0,b1,acc[0][1]);
            acc[0][2] = fmaf(a0,b2,acc[0][2]); acc[0][3] = fmaf(a0,b3,acc[0][3]);
            acc[1][0] = fmaf(a1,b0,acc[1][0]); acc[1][1] = fmaf(a1,b1,acc[1][1]);
            acc[1][2] = fmaf(a1,b2,acc[1][2]); acc[1][3] = fmaf(a1,b3,acc[1][3]);
            acc[2][0] = fmaf(a2,b0,acc[2][0]); acc[2][1] = fmaf(a2,b1,acc[2][1]);
            acc[2][2] = fmaf(a2,b2,acc[2][2]); acc[2][3] = fmaf(a2,b3,acc[2][3]);
            acc[3][0] = fmaf(a3,b0,acc[3][0]); acc[3][1] = fmaf(a3,b1,acc[3][1]);
            acc[3][2] = fmaf(a3,b2,acc[3][2]); acc[3][3] = fmaf(a3,b3,acc[3][3]);
        }
        __syncthreads();
    }

    int bb = head >> 4, h = head & 15;
    #pragma unroll
    for (int i = 0; i < 4; i++) {
        int s = byt*64 + ty*4 + i;
        #pragma unroll
        for (int j = 0; j < 4; j++) {
            int d = tx*4 + j;
            g_vals[((size_t)bb*S_ + s)*E_ + h*HD_ + d] = acc[i][j];
        }
    }
}

// ---------------------------------------------------------------------------
// Kernel 5: output projection  o[8192,1024] = vals @ w_o + b_o  -> d_out
// Same 128x128x8 SGEMM.
// ---------------------------------------------------------------------------
__global__ void __launch_bounds__(256) out_gemm_kernel(
    const float* __restrict__ Wo, const float* __restrict__ bo,
    float* __restrict__ out)
{
    const int N = E_, K = E_;
    __shared__ float As[8][128];
    __shared__ float Bs[8][128];
    int tid = threadIdx.x;
    int bx = blockIdx.x, by = blockIdx.y;

    int aRow = tid >> 1;
    int aCol = (tid & 1) * 4;
    int bRow = tid >> 5;
    int bCol = (tid & 31) * 4;
    int ty = tid >> 4, tx = tid & 15;

    float acc[8][8];
    #pragma unroll
    for (int i = 0; i < 8; i++)
        #pragma unroll
        for (int j = 0; j < 8; j++) acc[i][j] = 0.f;

    const float* Aptr = g_vals + (size_t)(by*128 + aRow)*K + aCol;
    const float* Bptr = Wo + (size_t)bRow*N + bx*128 + bCol;

    for (int k0 = 0; k0 < K; k0 += 8) {
        float4 a4 = *(const float4*)(Aptr + k0);
        As[aCol+0][aRow] = a4.x; As[aCol+1][aRow] = a4.y;
        As[aCol+2][aRow] = a4.z; As[aCol+3][aRow] = a4.w;
        float4 b4 = *(const float4*)(Bptr + (size_t)k0*N);
        *(float4*)&Bs[bRow][bCol] = b4;
        __syncthreads();
        #pragma unroll
        for (int k = 0; k < 8; k++) {
            float ar[8], br[8];
            *(float4*)(ar)   = *(float4*)&As[k][ty*8];
            *(float4*)(ar+4) = *(float4*)&As[k][ty*8+4];
            *(float4*)(br)   = *(float4*)&Bs[k][tx*8];
            *(float4*)(br+4) = *(float4*)&Bs[k][tx*8+4];
            #pragma unroll
            for (int i = 0; i < 8; i++)
                #pragma unroll
                for (int j = 0; j < 8; j++)
                    acc[i][j] = fmaf(ar[i], br[j], acc[i][j]);
        }
        __syncthreads();
    }

    #pragma unroll
    for (int i = 0; i < 8; i++) {
        int m = by*128 + ty*8 + i;
        #pragma unroll
        for (int j = 0; j < 8; j++) {
            int n = bx*128 + tx*8 + j;
            out[(size_t)m*N + n] = acc[i][j] + bo[n];
        }
    }
}

// ---------------------------------------------------------------------------
extern "C" void kernel_launch(void* const* d_in, const int* in_sizes, int n_in,
                              void* d_out, int out_size)
{
    const float* x     = (const float*)d_in[0];   // [B,S,E]
    const float* w_qkv = (const float*)d_in[1];   // [E,3E]
    const float* b_qkv = (const float*)d_in[2];   // [3E]
    const float* w_o   = (const float*)d_in[3];   // [E,E]
    const float* b_o   = (const float*)d_in[4];   // [E]
    // d_in[5] = mask (causal, hardcoded)

    float* o_out    = (float*)d_out;                       // [B,S,E]
    float* attn_out = o_out + (size_t)B_ * S_ * E_;        // [B,H,S,S]

    // 1. QKV projection + scatter
    {
        dim3 grid(N3E/128, (B_*S_)/128);   // (24, 64)
        qkv_gemm_kernel<<<grid, 256>>>(x, w_qkv, b_qkv);
    }
    // 2. causal logits
    {
        dim3 grid(S_/64, S_/64, BH_);      // (32, 32, 64)
        logits_kernel<<<grid, 256>>>(attn_out);
    }
    // 3. softmax rows
    {
        softmax_kernel<<<BH_ * S_, 256>>>(attn_out);
    }
    // 4. attn @ V
    {
        dim3 grid(1, S_/64, BH_);          // (1, 32, 64)
        av_kernel<<<grid, 256>>>(attn_out);
    }
    // 5. output projection
    {
        dim3 grid(E_/128, (B_*S_)/128);    // (8, 64)
        out_gemm_kernel<<<grid, 256>>>(w_o, b_o, o_out);
    }
}

// round 2
// speedup vs baseline: 1.1180x; 1.1180x over previous
#include <cuda_runtime.h>
#include <cuda_bf16.h>
#include <math.h>

// Problem constants
#define B_  4
#define S_  2048
#define E_  1024
#define H_  16
#define HD_ 64
#define BH_ (B_*H_)           // 64
#define N3E (3*E_)            // 3072

// Scratch (device globals; allocation-free)
__device__ float g_q[(size_t)BH_ * S_ * HD_];     // [B,H,S,HD]
__device__ float g_k[(size_t)BH_ * S_ * HD_];
__device__ float g_v[(size_t)BH_ * S_ * HD_];
__device__ float g_vals[(size_t)B_ * S_ * E_];    // [B,S,E]

// ---------------------------------------------------------------------------
// Kernel 1: QKV GEMM  C[8192,3072] = X[8192,1024] @ W[1024,3072] + bias,
// scattered into g_q/g_k/g_v with [B,H,S,HD] layout.
// ---------------------------------------------------------------------------
__global__ void __launch_bounds__(256) qkv_gemm_kernel(
    const float* __restrict__ X, const float* __restrict__ W,
    const float* __restrict__ bias)
{
    const int N = N3E, K = E_;
    __shared__ float As[8][128];
    __shared__ float Bs[8][128];
    int tid = threadIdx.x;
    int bx = blockIdx.x, by = blockIdx.y;

    int aRow = tid >> 1;
    int aCol = (tid & 1) * 4;
    int bRow = tid >> 5;
    int bCol = (tid & 31) * 4;
    int ty = tid >> 4, tx = tid & 15;

    float acc[8][8];
    #pragma unroll
    for (int i = 0; i < 8; i++)
        #pragma unroll
        for (int j = 0; j < 8; j++) acc[i][j] = 0.f;

    const float* Aptr = X + (size_t)(by*128 + aRow)*K + aCol;
    const float* Bptr = W + (size_t)bRow*N + bx*128 + bCol;

    for (int k0 = 0; k0 < K; k0 += 8) {
        float4 a4 = *(const float4*)(Aptr + k0);
        As[aCol+0][aRow] = a4.x; As[aCol+1][aRow] = a4.y;
        As[aCol+2][aRow] = a4.z; As[aCol+3][aRow] = a4.w;
        float4 b4 = *(const float4*)(Bptr + (size_t)k0*N);
        *(float4*)&Bs[bRow][bCol] = b4;
        __syncthreads();
        #pragma unroll
        for (int k = 0; k < 8; k++) {
            float ar[8], br[8];
            *(float4*)(ar)   = *(float4*)&As[k][ty*8];
            *(float4*)(ar+4) = *(float4*)&As[k][ty*8+4];
            *(float4*)(br)   = *(float4*)&Bs[k][tx*8];
            *(float4*)(br+4) = *(float4*)&Bs[k][tx*8+4];
            #pragma unroll
            for (int i = 0; i < 8; i++)
                #pragma unroll
                for (int j = 0; j < 8; j++)
                    acc[i][j] = fmaf(ar[i], br[j], acc[i][j]);
        }
        __syncthreads();
    }

    #pragma unroll
    for (int i = 0; i < 8; i++) {
        int m = by*128 + ty*8 + i;
        int bb = m >> 11;
        int s  = m & 2047;
        #pragma unroll
        for (int j = 0; j < 8; j++) {
            int n = bx*128 + tx*8 + j;
            float val = acc[i][j] + bias[n];
            int h = n / 192;
            int r = n - h*192;
            size_t base = (((size_t)bb*H_ + h)*S_ + s)*HD_;
            if (r < 64)       g_q[base + r]       = val;
            else if (r < 128) g_k[base + r - 64]  = val;
            else              g_v[base + r - 128] = val;
        }
    }
}

// ---------------------------------------------------------------------------
// Kernel 2 (FUSED): per (head, 64-row query tile):
//   pass 1: stream K tiles, compute logits, online softmax stats,
//           write e = exp(l - m_running) to attn buffer, snapshot m per tile.
//   zero-fill the masked upper region.
//   pass 2: read e back, rescale to final probs, write probs, accumulate p@V.
// 256 threads, 4x4 per thread over a 64x64 tile.
// ---------------------------------------------------------------------------
__global__ void __launch_bounds__(256) attn_fused_kernel(float* __restrict__ attn)
{
    const int head = blockIdx.y;
    const int qt   = (int)gridDim.x - 1 - (int)blockIdx.x;  // heavy tiles first

    const float* qbase = g_q + (size_t)head*S_*HD_;
    const float* kbase = g_k + (size_t)head*S_*HD_;
    const float* vbase = g_v + (size_t)head*S_*HD_;
    float* out = attn + (size_t)head*S_*S_;

    const int tid = threadIdx.x;
    const int ty = tid >> 4, tx = tid & 15;

    __shared__ float Qs[64][68];     // pass1: Q^T [d][r]; pass2: P [r][k]
    __shared__ float Ks[64][68];     // pass1: K^T [d][c]; pass2: V  [k][d]
    __shared__ float msnap[32][64];  // running max snapshot [ktile][row]

    // ---- zero-fill masked region (cols >= (qt+1)*64) ----
    {
        const int c0 = (qt + 1) * 64;
        const int nc = S_ - c0;
        if (nc > 0) {
            const int n4 = nc >> 2;
            const float4 z = make_float4(0.f, 0.f, 0.f, 0.f);
            for (int idx = tid; idx < 64 * n4; idx += 256) {
                int r = idx / n4;
                int c = (idx - r * n4) << 2;
                *(float4*)&out[(size_t)(qt*64 + r)*S_ + c0 + c] = z;
            }
        }
    }

    // ---- load Q tile transposed ----
    for (int idx = tid; idx < 64*16; idx += 256) {
        int r = idx >> 4;
        int c = (idx & 15) * 4;
        float4 q4 = *(const float4*)&qbase[(size_t)(qt*64 + r)*HD_ + c];
        Qs[c+0][r] = q4.x; Qs[c+1][r] = q4.y; Qs[c+2][r] = q4.z; Qs[c+3][r] = q4.w;
    }

    float m_run[4], s_run[4];
    #pragma unroll
    for (int i = 0; i < 4; i++) { m_run[i] = -INFINITY; s_run[i] = 0.f; }

    const float scale = 0.125f;  // 1/sqrt(64)

    // =================== PASS 1 ===================
    for (int kt = 0; kt <= qt; kt++) {
        __syncthreads();   // protect Ks (and Qs on first iter) before overwrite/use
        for (int idx = tid; idx < 64*16; idx += 256) {
            int r = idx >> 4;
            int c = (idx & 15) * 4;
            float4 k4 = *(const float4*)&kbase[(size_t)(kt*64 + r)*HD_ + c];
            Ks[c+0][r] = k4.x; Ks[c+1][r] = k4.y; Ks[c+2][r] = k4.z; Ks[c+3][r] = k4.w;
        }
        __syncthreads();

        float acc[4][4];
        #pragma unroll
        for (int i = 0; i < 4; i++)
            #pragma unroll
            for (int j = 0; j < 4; j++) acc[i][j] = 0.f;

        #pragma unroll 4
        for (int k = 0; k < 64; k++) {
            float4 a = *(float4*)&Qs[k][ty*4];
            float4 b = *(float4*)&Ks[k][tx*4];
            acc[0][0] = fmaf(a.x,b.x,acc[0][0]); acc[0][1] = fmaf(a.x,b.y,acc[0][1]);
            acc[0][2] = fmaf(a.x,b.z,acc[0][2]); acc[0][3] = fmaf(a.x,b.w,acc[0][3]);
            acc[1][0] = fmaf(a.y,b.x,acc[1][0]); acc[1][1] = fmaf(a.y,b.y,acc[1][1]);
            acc[1][2] = fmaf(a.y,b.z,acc[1][2]); acc[1][3] = fmaf(a.y,b.w,acc[1][3]);
            acc[2][0] = fmaf(a.z,b.x,acc[2][0]); acc[2][1] = fmaf(a.z,b.y,acc[2][1]);
            acc[2][2] = fmaf(a.z,b.z,acc[2][2]); acc[2][3] = fmaf(a.z,b.w,acc[2][3]);
            acc[3][0] = fmaf(a.w,b.x,acc[3][0]); acc[3][1] = fmaf(a.w,b.y,acc[3][1]);
            acc[3][2] = fmaf(a.w,b.z,acc[3][2]); acc[3][3] = fmaf(a.w,b.w,acc[3][3]);
        }

        const bool diag = (kt == qt);
        #pragma unroll
        for (int i = 0; i < 4; i++) {
            const int row = qt*64 + ty*4 + i;
            float l[4]; bool valid[4];
            #pragma unroll
            for (int j = 0; j < 4; j++) {
                int col = kt*64 + tx*4 + j;
                l[j] = acc[i][j] * scale;
                valid[j] = !diag || (col <= row);
            }
            float t = -INFINITY;
            #pragma unroll
            for (int j = 0; j < 4; j++) t = fmaxf(t, valid[j] ? l[j] : -INFINITY);
            #pragma unroll
            for (int o = 8; o > 0; o >>= 1)
                t = fmaxf(t, __shfl_xor_sync(0xffffffffu, t, o));
            float m_new = fmaxf(m_run[i], t);

            float e[4], rs = 0.f;
            #pragma unroll
            for (int j = 0; j < 4; j++) {
                e[j] = valid[j] ? __expf(l[j] - m_new) : 0.f;
                rs += e[j];
            }
            *(float4*)&out[(size_t)row*S_ + kt*64 + tx*4] =
                make_float4(e[0], e[1], e[2], e[3]);
            #pragma unroll
            for (int o = 8; o > 0; o >>= 1)
                rs += __shfl_xor_sync(0xffffffffu, rs, o);

            s_run[i] = s_run[i] * __expf(m_run[i] - m_new) + rs;
            m_run[i] = m_new;
            if (tx == 0) msnap[kt][ty*4 + i] = m_new;
        }
    }

    // =================== PASS 2 ===================
    float inv_s[4], mf[4];
    #pragma unroll
    for (int i = 0; i < 4; i++) { inv_s[i] = 1.f / s_run[i]; mf[i] = m_run[i]; }

    float vacc[4][4];
    #pragma unroll
    for (int i = 0; i < 4; i++)
        #pragma unroll
        for (int j = 0; j < 4; j++) vacc[i][j] = 0.f;

    for (int kt = 0; kt <= qt; kt++) {
        __syncthreads();   // previous-iter AV done; also orders pass1 smem vs reuse
        // V tile -> Ks as [k][d]
        for (int idx = tid; idx < 64*16; idx += 256) {
            int r = idx >> 4;
            int c = (idx & 15) * 4;
            *(float4*)&Ks[r][c] = *(const float4*)&vbase[(size_t)(kt*64 + r)*HD_ + c];
        }
        // read e, rescale to p, write p, stage P into Qs as [r][k]
        #pragma unroll
        for (int i = 0; i < 4; i++) {
            const int row = qt*64 + ty*4 + i;
            float4 e4 = *(float4*)&out[(size_t)row*S_ + kt*64 + tx*4];
            float f = __expf(msnap[kt][ty*4 + i] - mf[i]) * inv_s[i];
            e4.x *= f; e4.y *= f; e4.z *= f; e4.w *= f;
            *(float4*)&out[(size_t)row*S_ + kt*64 + tx*4] = e4;
            *(float4*)&Qs[ty*4 + i][tx*4] = e4;
        }
        __syncthreads();

        #pragma unroll 4
        for (int k = 0; k < 64; k++) {
            float a0 = Qs[ty*4+0][k];
            float a1 = Qs[ty*4+1][k];
            float a2 = Qs[ty*4+2][k];
            float a3 = Qs[ty*4+3][k];
            float4 b = *(float4*)&Ks[k][tx*4];
            vacc[0][0] = fmaf(a0,b.x,vacc[0][0]); vacc[0][1] = fmaf(a0,b.y,vacc[0][1]);
            vacc[0][2] = fmaf(a0,b.z,vacc[0][2]); vacc[0][3] = fmaf(a0,b.w,vacc[0][3]);
            vacc[1][0] = fmaf(a1,b.x,vacc[1][0]); vacc[1][1] = fmaf(a1,b.y,vacc[1][1]);
            vacc[1][2] = fmaf(a1,b.z,vacc[1][2]); vacc[1][3] = fmaf(a1,b.w,vacc[1][3]);
            vacc[2][0] = fmaf(a2,b.x,vacc[2][0]); vacc[2][1] = fmaf(a2,b.y,vacc[2][1]);
            vacc[2][2] = fmaf(a2,b.z,vacc[2][2]); vacc[2][3] = fmaf(a2,b.w,vacc[2][3]);
            vacc[3][0] = fmaf(a3,b.x,vacc[3][0]); vacc[3][1] = fmaf(a3,b.y,vacc[3][1]);
            vacc[3][2] = fmaf(a3,b.z,vacc[3][2]); vacc[3][3] = fmaf(a3,b.w,vacc[3][3]);
        }
    }

    // write vals [B,S,E]
    const int bb = head >> 4, h = head & 15;
    #pragma unroll
    for (int i = 0; i < 4; i++) {
        int s = qt*64 + ty*4 + i;
        *(float4*)&g_vals[((size_t)bb*S_ + s)*E_ + h*HD_ + tx*4] =
            make_float4(vacc[i][0], vacc[i][1], vacc[i][2], vacc[i][3]);
    }
}

// ---------------------------------------------------------------------------
// Kernel 3: output projection  o[8192,1024] = vals @ w_o + b_o  -> d_out
// ---------------------------------------------------------------------------
__global__ void __launch_bounds__(256) out_gemm_kernel(
    const float* __restrict__ Wo, const float* __restrict__ bo,
    float* __restrict__ out)
{
    const int N = E_, K = E_;
    __shared__ float As[8][128];
    __shared__ float Bs[8][128];
    int tid = threadIdx.x;
    int bx = blockIdx.x, by = blockIdx.y;

    int aRow = tid >> 1;
    int aCol = (tid & 1) * 4;
    int bRow = tid >> 5;
    int bCol = (tid & 31) * 4;
    int ty = tid >> 4, tx = tid & 15;

    float acc[8][8];
    #pragma unroll
    for (int i = 0; i < 8; i++)
        #pragma unroll
        for (int j = 0; j < 8; j++) acc[i][j] = 0.f;

    const float* Aptr = g_vals + (size_t)(by*128 + aRow)*K + aCol;
    const float* Bptr = Wo + (size_t)bRow*N + bx*128 + bCol;

    for (int k0 = 0; k0 < K; k0 += 8) {
        float4 a4 = *(const float4*)(Aptr + k0);
        As[aCol+0][aRow] = a4.x; As[aCol+1][aRow] = a4.y;
        As[aCol+2][aRow] = a4.z; As[aCol+3][aRow] = a4.w;
        float4 b4 = *(const float4*)(Bptr + (size_t)k0*N);
        *(float4*)&Bs[bRow][bCol] = b4;
        __syncthreads();
        #pragma unroll
        for (int k = 0; k < 8; k++) {
            float ar[8], br[8];
            *(float4*)(ar)   = *(float4*)&As[k][ty*8];
            *(float4*)(ar+4) = *(float4*)&As[k][ty*8+4];
            *(float4*)(br)   = *(float4*)&Bs[k][tx*8];
            *(float4*)(br+4) = *(float4*)&Bs[k][tx*8+4];
            #pragma unroll
            for (int i = 0; i < 8; i++)
                #pragma unroll
                for (int j = 0; j < 8; j++)
                    acc[i][j] = fmaf(ar[i], br[j], acc[i][j]);
        }
        __syncthreads();
    }

    #pragma unroll
    for (int i = 0; i < 8; i++) {
        int m = by*128 + ty*8 + i;
        #pragma unroll
        for (int j = 0; j < 8; j++) {
            int n = bx*128 + tx*8 + j;
            out[(size_t)m*N + n] = acc[i][j] + bo[n];
        }
    }
}

// ---------------------------------------------------------------------------
extern "C" void kernel_launch(void* const* d_in, const int* in_sizes, int n_in,
                              void* d_out, int out_size)
{
    const float* x     = (const float*)d_in[0];   // [B,S,E]
    const float* w_qkv = (const float*)d_in[1];   // [E,3E]
    const float* b_qkv = (const float*)d_in[2];   // [3E]
    const float* w_o   = (const float*)d_in[3];   // [E,E]
    const float* b_o   = (const float*)d_in[4];   // [E]
    // d_in[5] = causal mask (hardcoded)

    float* o_out    = (float*)d_out;                       // [B,S,E]
    float* attn_out = o_out + (size_t)B_ * S_ * E_;        // [B,H,S,S]

    // 1. QKV projection + scatter
    {
        dim3 grid(N3E/128, (B_*S_)/128);
        qkv_gemm_kernel<<<grid, 256>>>(x, w_qkv, b_qkv);
    }
    // 2. fused logits + softmax + attn@V
    {
        dim3 grid(S_/64, BH_);      // (32, 64)
        attn_fused_kernel<<<grid, 256>>>(attn_out);
    }
    // 3. output projection
    {
        dim3 grid(E_/128, (B_*S_)/128);
        out_gemm_kernel<<<grid, 256>>>(w_o, b_o, o_out);
    }
}